// round 14
// baseline (speedup 1.0000x reference)
#include <cuda_runtime.h>
#include <cuda_bf16.h>
#include <cstdint>

#define IN_DIM  4096
#define OUT_DIM 4096
#define MX      8192          /* B*S = 4*2048 */
#define KE      12288         /* 3 * IN_DIM (split-bf16 K expansion) */

// ---------------------------------------------------------------------------
// Static device scratch (allocation inside kernel_launch is forbidden).
// A-side pattern over K': [hi | hi | lo]   B-side pattern: [hi | lo | hi]
// Segment products: hi*hi + hi*lo + lo*hi  ==> fp32-class accuracy in bf16 MMA.
// ---------------------------------------------------------------------------
__device__ __nv_bfloat16 g_Xe[(size_t)MX      * KE];  // x expanded      (A side)
__device__ __nv_bfloat16 g_Ye[(size_t)OUT_DIM * KE];  // centroid gather (A side)
__device__ __nv_bfloat16 g_Pe[(size_t)IN_DIM  * KE];  // Pi^T expanded   (B side)
__device__ __nv_bfloat16 g_We[(size_t)OUT_DIM * KE];  // W expanded      (B side)

__device__ __forceinline__ void split_bf16(float v, __nv_bfloat16 &h, __nv_bfloat16 &l) {
    h = __float2bfloat16(v);
    l = __float2bfloat16(v - __bfloat162float(h));
}

// ---------------------------------------------------------------------------
// Prep kernel 1: split x (fp32) -> Xe (A-side pattern hi,hi,lo)
// ---------------------------------------------------------------------------
__global__ void expand_x_kernel(const float* __restrict__ x) {
    int64_t idx = (int64_t)blockIdx.x * blockDim.x + threadIdx.x;
    if (idx >= (int64_t)MX * IN_DIM / 4) return;
    int64_t m  = idx / (IN_DIM / 4);
    int     k4 = (int)(idx % (IN_DIM / 4)) * 4;
    float4 v = reinterpret_cast<const float4*>(x)[idx];
    alignas(8) __nv_bfloat16 h[4];
    alignas(8) __nv_bfloat16 l[4];
    split_bf16(v.x, h[0], l[0]);
    split_bf16(v.y, h[1], l[1]);
    split_bf16(v.z, h[2], l[2]);
    split_bf16(v.w, h[3], l[3]);
    __nv_bfloat16* dst = g_Xe + m * KE + k4;
    *reinterpret_cast<uint2*>(dst)              = *reinterpret_cast<const uint2*>(h);
    *reinterpret_cast<uint2*>(dst + IN_DIM)     = *reinterpret_cast<const uint2*>(h);
    *reinterpret_cast<uint2*>(dst + 2 * IN_DIM) = *reinterpret_cast<const uint2*>(l);
}

// ---------------------------------------------------------------------------
// Prep kernel 2: gather centroids[indices] -> Ye (A-side pattern hi,hi,lo)
// ---------------------------------------------------------------------------
__global__ void expand_y_kernel(const int* __restrict__ idxs,
                                const float* __restrict__ cent) {
    int64_t idx = (int64_t)blockIdx.x * blockDim.x + threadIdx.x;
    if (idx >= (int64_t)OUT_DIM * IN_DIM / 4) return;
    int64_t o  = idx / (IN_DIM / 4);
    int     k4 = (int)(idx % (IN_DIM / 4)) * 4;
    int4 id = reinterpret_cast<const int4*>(idxs)[idx];
    alignas(8) __nv_bfloat16 h[4];
    alignas(8) __nv_bfloat16 l[4];
    split_bf16(__ldg(cent + id.x), h[0], l[0]);
    split_bf16(__ldg(cent + id.y), h[1], l[1]);
    split_bf16(__ldg(cent + id.z), h[2], l[2]);
    split_bf16(__ldg(cent + id.w), h[3], l[3]);
    __nv_bfloat16* dst = g_Ye + o * KE + k4;
    *reinterpret_cast<uint2*>(dst)              = *reinterpret_cast<const uint2*>(h);
    *reinterpret_cast<uint2*>(dst + IN_DIM)     = *reinterpret_cast<const uint2*>(h);
    *reinterpret_cast<uint2*>(dst + 2 * IN_DIM) = *reinterpret_cast<const uint2*>(l);
}

// ---------------------------------------------------------------------------
// Prep kernel 3: transpose Pi and split -> Pe[j][i'] (B-side pattern hi,lo,hi)
// ---------------------------------------------------------------------------
__global__ void expand_pi_kernel(const float* __restrict__ Pi) {
    __shared__ float tile[32][33];
    int bx = blockIdx.x, by = blockIdx.y;   // bx: j tiles, by: i tiles
    int tx = threadIdx.x, ty = threadIdx.y; // 32 x 8
#pragma unroll
    for (int s = 0; s < 4; s++) {
        int i = by * 32 + ty + s * 8;
        tile[ty + s * 8][tx] = Pi[(int64_t)i * IN_DIM + bx * 32 + tx];
    }
    __syncthreads();
#pragma unroll
    for (int s = 0; s < 4; s++) {
        int j = bx * 32 + ty + s * 8;
        int i = by * 32 + tx;
        float v = tile[tx][ty + s * 8];
        __nv_bfloat16 h, l;
        split_bf16(v, h, l);
        __nv_bfloat16* row = g_Pe + (int64_t)j * KE;
        row[i]              = h;
        row[IN_DIM + i]     = l;
        row[2 * IN_DIM + i] = h;
    }
}

// ---------------------------------------------------------------------------
// bf16 TN GEMM: C[m,n] = sum_k A[m,k] * B[n,k]   (K = KE, N = 4096)
// 128x128x32 CTA tile, 8 warps (2x4), warp tile 64x32, mma.m16n8k16,
// cp.async 2-stage double buffer, XOR-swizzled smem (conflict-free STS + LDS).
// EPI==1: C *= row_norms[m], re-split to We (B-side pattern)
// EPI==0: C += bias[n], write fp32 out
// ---------------------------------------------------------------------------
__device__ __forceinline__ int swoff(int r, int c) {
    // 128 rows x 32 bf16 (64B) per row; swizzle 16B chunks by (r>>1)&3
    return (r << 5) + ((((c >> 3) ^ (r >> 1)) & 3) << 3) + (c & 7);
}

__device__ __forceinline__ void mma16816(float* c, const uint32_t* a, const uint32_t* b) {
    asm volatile(
        "mma.sync.aligned.m16n8k16.row.col.f32.bf16.bf16.f32 "
        "{%0,%1,%2,%3}, {%4,%5,%6,%7}, {%8,%9}, {%0,%1,%2,%3};\n"
        : "+f"(c[0]), "+f"(c[1]), "+f"(c[2]), "+f"(c[3])
        : "r"(a[0]), "r"(a[1]), "r"(a[2]), "r"(a[3]), "r"(b[0]), "r"(b[1]));
}

template <int EPI>
__global__ __launch_bounds__(256, 2)
void gemm_kernel(const float* __restrict__ vec, float* __restrict__ outF) {
    constexpr int BK = 32;
    constexpr int NT = KE / BK;

    const __nv_bfloat16* __restrict__ A = (EPI == 1) ? g_Ye : g_Xe;
    const __nv_bfloat16* __restrict__ B = (EPI == 1) ? g_Pe : g_We;

    __shared__ __nv_bfloat16 sA[2][128 * BK];
    __shared__ __nv_bfloat16 sB[2][128 * BK];

    const int tid  = threadIdx.x;
    const int lane = tid & 31;
    const int warp = tid >> 5;
    const int wm   = (warp >> 2) * 64;  // warp M offset (2 rows of warps)
    const int wn   = (warp & 3) * 32;   // warp N offset (4 cols of warps)
    const int g    = lane >> 2;
    const int tig  = lane & 3;

    const int m0 = blockIdx.y * 128;
    const int n0 = blockIdx.x * 128;

    // loader mapping: 4 threads per row (16B chunks), 64 rows per pass
    const int lr = tid >> 2;
    const int lc = (tid & 3) << 3;

    const __nv_bfloat16* gA = A + (int64_t)(m0 + lr) * KE + lc;
    const __nv_bfloat16* gB = B + (int64_t)(n0 + lr) * KE + lc;

    const uint32_t sAb = (uint32_t)__cvta_generic_to_shared(&sA[0][0]);
    const uint32_t sBb = (uint32_t)__cvta_generic_to_shared(&sB[0][0]);
    const uint32_t dA0 = sAb + swoff(lr, lc) * 2;
    const uint32_t dA1 = sAb + swoff(lr + 64, lc) * 2;
    const uint32_t dB0 = sBb + swoff(lr, lc) * 2;
    const uint32_t dB1 = sBb + swoff(lr + 64, lc) * 2;
    constexpr uint32_t STG = 128 * BK * 2;  // 8KB per stage

    float acc[4][4][4];
#pragma unroll
    for (int i = 0; i < 4; i++)
#pragma unroll
        for (int j = 0; j < 4; j++)
#pragma unroll
            for (int q = 0; q < 4; q++) acc[i][j][q] = 0.f;

    auto load_tile = [&](int kt, int s) {
        const __nv_bfloat16* a = gA + kt * BK;
        const __nv_bfloat16* b = gB + kt * BK;
        uint32_t off = s * STG;
        asm volatile("cp.async.cg.shared.global [%0], [%1], 16;\n" :: "r"(dA0 + off), "l"(a));
        asm volatile("cp.async.cg.shared.global [%0], [%1], 16;\n" :: "r"(dA1 + off), "l"(a + (int64_t)64 * KE));
        asm volatile("cp.async.cg.shared.global [%0], [%1], 16;\n" :: "r"(dB0 + off), "l"(b));
        asm volatile("cp.async.cg.shared.global [%0], [%1], 16;\n" :: "r"(dB1 + off), "l"(b + (int64_t)64 * KE));
        asm volatile("cp.async.commit_group;\n");
    };

    load_tile(0, 0);

    for (int kt = 0; kt < NT; kt++) {
        const int s = kt & 1;
        if (kt + 1 < NT) {
            load_tile(kt + 1, s ^ 1);
            asm volatile("cp.async.wait_group 1;\n" ::: "memory");
        } else {
            asm volatile("cp.async.wait_group 0;\n" ::: "memory");
        }
        __syncthreads();

        const __nv_bfloat16* tA = sA[s];
        const __nv_bfloat16* tB = sB[s];
#pragma unroll
        for (int ks = 0; ks < 2; ks++) {
            const int kb = ks * 16 + 2 * tig;
            uint32_t af[4][4], bf[4][2];
#pragma unroll
            for (int mt = 0; mt < 4; mt++) {
                const int r = wm + mt * 16 + g;
                af[mt][0] = *reinterpret_cast<const uint32_t*>(tA + swoff(r,     kb));
                af[mt][1] = *reinterpret_cast<const uint32_t*>(tA + swoff(r + 8, kb));
                af[mt][2] = *reinterpret_cast<const uint32_t*>(tA + swoff(r,     kb + 8));
                af[mt][3] = *reinterpret_cast<const uint32_t*>(tA + swoff(r + 8, kb + 8));
            }
#pragma unroll
            for (int nt = 0; nt < 4; nt++) {
                const int r = wn + nt * 8 + g;
                bf[nt][0] = *reinterpret_cast<const uint32_t*>(tB + swoff(r, kb));
                bf[nt][1] = *reinterpret_cast<const uint32_t*>(tB + swoff(r, kb + 8));
            }
#pragma unroll
            for (int mt = 0; mt < 4; mt++)
#pragma unroll
                for (int nt = 0; nt < 4; nt++)
                    mma16816(acc[mt][nt], af[mt], bf[nt]);
        }
        __syncthreads();
    }

    // Epilogue
#pragma unroll
    for (int mt = 0; mt < 4; mt++) {
        const int row = m0 + wm + mt * 16 + g;
#pragma unroll
        for (int nt = 0; nt < 4; nt++) {
            const int col = n0 + wn + nt * 8 + 2 * tig;
            const float* c = acc[mt][nt];
            if (EPI == 0) {
                const float b0 = vec[col], b1 = vec[col + 1];
                float* o0 = outF + (int64_t)row * OUT_DIM + col;
                float* o1 = outF + (int64_t)(row + 8) * OUT_DIM + col;
                o0[0] = c[0] + b0;
                o0[1] = c[1] + b1;
                o1[0] = c[2] + b0;
                o1[1] = c[3] + b1;
            } else {
                const float r0 = vec[row], r1 = vec[row + 8];
                __nv_bfloat16* w0 = g_We + (int64_t)row * KE + col;
                __nv_bfloat16* w1 = g_We + (int64_t)(row + 8) * KE + col;
                __nv_bfloat16 h, l;
                float w;
                w = c[0] * r0; split_bf16(w, h, l); w0[0] = h; w0[IN_DIM]     = l; w0[2 * IN_DIM]     = h;
                w = c[1] * r0; split_bf16(w, h, l); w0[1] = h; w0[IN_DIM + 1] = l; w0[2 * IN_DIM + 1] = h;
                w = c[2] * r1; split_bf16(w, h, l); w1[0] = h; w1[IN_DIM]     = l; w1[2 * IN_DIM]     = h;
                w = c[3] * r1; split_bf16(w, h, l); w1[1] = h; w1[IN_DIM + 1] = l; w1[2 * IN_DIM + 1] = h;
            }
        }
    }
}

// ---------------------------------------------------------------------------
// Launch: expand(x, yhat, piT) -> GEMM1 (W = rn * Yhat@Pi, re-split) -> GEMM2
// All launches on the default stream; graph-capturable, allocation-free.
// ---------------------------------------------------------------------------
extern "C" void kernel_launch(void* const* d_in, const int* in_sizes, int n_in,
                              void* d_out, int out_size) {
    const float* x         = (const float*)d_in[0];
    const int*   indices   = (const int*)  d_in[1];
    const float* centroids = (const float*)d_in[2];
    const float* Pi        = (const float*)d_in[3];
    const float* row_norms = (const float*)d_in[4];
    const float* bias      = (const float*)d_in[5];
    float*       out       = (float*)d_out;
    (void)in_sizes; (void)n_in; (void)out_size;

    {
        int64_t tot = (int64_t)MX * IN_DIM / 4;
        expand_x_kernel<<<(unsigned)((tot + 255) / 256), 256>>>(x);
    }
    {
        int64_t tot = (int64_t)OUT_DIM * IN_DIM / 4;
        expand_y_kernel<<<(unsigned)((tot + 255) / 256), 256>>>(indices, centroids);
    }
    {
        dim3 grid(IN_DIM / 32, IN_DIM / 32), blk(32, 8);
        expand_pi_kernel<<<grid, blk>>>(Pi);
    }
    {   // GEMM1: W[o,j], M = OUT_DIM
        dim3 grid(IN_DIM / 128, OUT_DIM / 128);
        gemm_kernel<1><<<grid, 256>>>(row_norms, nullptr);
    }
    {   // GEMM2: out[m,o] = x @ W^T + bias, M = MX
        dim3 grid(OUT_DIM / 128, MX / 128);
        gemm_kernel<0><<<grid, 256>>>(bias, out);
    }
}

// round 15
// speedup vs baseline: 1.0085x; 1.0085x over previous
#include <cuda_runtime.h>
#include <cuda_bf16.h>
#include <cstdint>

#define IN_DIM  4096
#define OUT_DIM 4096
#define MX      8192          /* B*S = 4*2048 */
#define KE      12288         /* 3 * IN_DIM (split-bf16 K expansion) */

// ---------------------------------------------------------------------------
// Static device scratch (allocation inside kernel_launch is forbidden).
// A-side pattern over K': [hi | hi | lo]   B-side pattern: [hi | lo | hi]
// Segment products: hi*hi + hi*lo + lo*hi  ==> fp32-class accuracy in bf16 MMA.
// ---------------------------------------------------------------------------
__device__ __nv_bfloat16 g_Xe[(size_t)MX      * KE];  // x expanded      (A side)
__device__ __nv_bfloat16 g_Ye[(size_t)OUT_DIM * KE];  // centroid gather (A side)
__device__ __nv_bfloat16 g_Pe[(size_t)IN_DIM  * KE];  // Pi^T expanded   (B side)
__device__ __nv_bfloat16 g_We[(size_t)OUT_DIM * KE];  // W expanded      (B side)

__device__ __forceinline__ void split_bf16(float v, __nv_bfloat16 &h, __nv_bfloat16 &l) {
    h = __float2bfloat16(v);
    l = __float2bfloat16(v - __bfloat162float(h));
}

// ---------------------------------------------------------------------------
// Prep kernel 1: split x (fp32) -> Xe (A-side pattern hi,hi,lo)
// ---------------------------------------------------------------------------
__global__ void expand_x_kernel(const float* __restrict__ x) {
    int64_t idx = (int64_t)blockIdx.x * blockDim.x + threadIdx.x;
    if (idx >= (int64_t)MX * IN_DIM / 4) return;
    int64_t m  = idx / (IN_DIM / 4);
    int     k4 = (int)(idx % (IN_DIM / 4)) * 4;
    float4 v = reinterpret_cast<const float4*>(x)[idx];
    alignas(8) __nv_bfloat16 h[4];
    alignas(8) __nv_bfloat16 l[4];
    split_bf16(v.x, h[0], l[0]);
    split_bf16(v.y, h[1], l[1]);
    split_bf16(v.z, h[2], l[2]);
    split_bf16(v.w, h[3], l[3]);
    __nv_bfloat16* dst = g_Xe + m * KE + k4;
    *reinterpret_cast<uint2*>(dst)              = *reinterpret_cast<const uint2*>(h);
    *reinterpret_cast<uint2*>(dst + IN_DIM)     = *reinterpret_cast<const uint2*>(h);
    *reinterpret_cast<uint2*>(dst + 2 * IN_DIM) = *reinterpret_cast<const uint2*>(l);
}

// ---------------------------------------------------------------------------
// Prep kernel 2: gather centroids[indices] -> Ye (A-side pattern hi,hi,lo)
// ---------------------------------------------------------------------------
__global__ void expand_y_kernel(const int* __restrict__ idxs,
                                const float* __restrict__ cent) {
    int64_t idx = (int64_t)blockIdx.x * blockDim.x + threadIdx.x;
    if (idx >= (int64_t)OUT_DIM * IN_DIM / 4) return;
    int64_t o  = idx / (IN_DIM / 4);
    int     k4 = (int)(idx % (IN_DIM / 4)) * 4;
    int4 id = reinterpret_cast<const int4*>(idxs)[idx];
    alignas(8) __nv_bfloat16 h[4];
    alignas(8) __nv_bfloat16 l[4];
    split_bf16(__ldg(cent + id.x), h[0], l[0]);
    split_bf16(__ldg(cent + id.y), h[1], l[1]);
    split_bf16(__ldg(cent + id.z), h[2], l[2]);
    split_bf16(__ldg(cent + id.w), h[3], l[3]);
    __nv_bfloat16* dst = g_Ye + o * KE + k4;
    *reinterpret_cast<uint2*>(dst)              = *reinterpret_cast<const uint2*>(h);
    *reinterpret_cast<uint2*>(dst + IN_DIM)     = *reinterpret_cast<const uint2*>(h);
    *reinterpret_cast<uint2*>(dst + 2 * IN_DIM) = *reinterpret_cast<const uint2*>(l);
}

// ---------------------------------------------------------------------------
// Prep kernel 3: transpose Pi and split -> Pe[j][i'] (B-side pattern hi,lo,hi)
// ---------------------------------------------------------------------------
__global__ void expand_pi_kernel(const float* __restrict__ Pi) {
    __shared__ float tile[32][33];
    int bx = blockIdx.x, by = blockIdx.y;   // bx: j tiles, by: i tiles
    int tx = threadIdx.x, ty = threadIdx.y; // 32 x 8
#pragma unroll
    for (int s = 0; s < 4; s++) {
        int i = by * 32 + ty + s * 8;
        tile[ty + s * 8][tx] = Pi[(int64_t)i * IN_DIM + bx * 32 + tx];
    }
    __syncthreads();
#pragma unroll
    for (int s = 0; s < 4; s++) {
        int j = bx * 32 + ty + s * 8;
        int i = by * 32 + tx;
        float v = tile[tx][ty + s * 8];
        __nv_bfloat16 h, l;
        split_bf16(v, h, l);
        __nv_bfloat16* row = g_Pe + (int64_t)j * KE;
        row[i]              = h;
        row[IN_DIM + i]     = l;
        row[2 * IN_DIM + i] = h;
    }
}

// ---------------------------------------------------------------------------
// bf16 TN GEMM: C[m,n] = sum_k A[m,k] * B[n,k]   (K = KE, N = 4096)
// 128x128x32 CTA tile, 8 warps (2x4), warp tile 64x32, mma.m16n8k16,
// cp.async 2-stage double buffer, XOR-swizzled smem (conflict-free STS + LDS).
// EPI==1: C *= row_norms[m], re-split to We (B-side pattern)
// EPI==0: C += bias[n], write fp32 out
// ---------------------------------------------------------------------------
__device__ __forceinline__ int swoff(int r, int c) {
    // 128 rows x 32 bf16 (64B) per row; swizzle 16B chunks by (r>>1)&3
    return (r << 5) + ((((c >> 3) ^ (r >> 1)) & 3) << 3) + (c & 7);
}

__device__ __forceinline__ void mma16816(float* c, const uint32_t* a, const uint32_t* b) {
    asm volatile(
        "mma.sync.aligned.m16n8k16.row.col.f32.bf16.bf16.f32 "
        "{%0,%1,%2,%3}, {%4,%5,%6,%7}, {%8,%9}, {%0,%1,%2,%3};\n"
        : "+f"(c[0]), "+f"(c[1]), "+f"(c[2]), "+f"(c[3])
        : "r"(a[0]), "r"(a[1]), "r"(a[2]), "r"(a[3]), "r"(b[0]), "r"(b[1]));
}

template <int EPI>
__global__ __launch_bounds__(256, 2)
void gemm_kernel(const float* __restrict__ vec, float* __restrict__ outF) {
    constexpr int BK = 32;
    constexpr int NT = KE / BK;

    const __nv_bfloat16* __restrict__ A = (EPI == 1) ? g_Ye : g_Xe;
    const __nv_bfloat16* __restrict__ B = (EPI == 1) ? g_Pe : g_We;

    __shared__ __nv_bfloat16 sA[2][128 * BK];
    __shared__ __nv_bfloat16 sB[2][128 * BK];

    const int tid  = threadIdx.x;
    const int lane = tid & 31;
    const int warp = tid >> 5;
    const int wm   = (warp >> 2) * 64;  // warp M offset (2 rows of warps)
    const int wn   = (warp & 3) * 32;   // warp N offset (4 cols of warps)
    const int g    = lane >> 2;
    const int tig  = lane & 3;

    const int m0 = blockIdx.y * 128;
    const int n0 = blockIdx.x * 128;

    // loader mapping: 4 threads per row (16B chunks), 64 rows per pass
    const int lr = tid >> 2;
    const int lc = (tid & 3) << 3;

    const __nv_bfloat16* gA = A + (int64_t)(m0 + lr) * KE + lc;
    const __nv_bfloat16* gB = B + (int64_t)(n0 + lr) * KE + lc;

    const uint32_t sAb = (uint32_t)__cvta_generic_to_shared(&sA[0][0]);
    const uint32_t sBb = (uint32_t)__cvta_generic_to_shared(&sB[0][0]);
    const uint32_t dA0 = sAb + swoff(lr, lc) * 2;
    const uint32_t dA1 = sAb + swoff(lr + 64, lc) * 2;
    const uint32_t dB0 = sBb + swoff(lr, lc) * 2;
    const uint32_t dB1 = sBb + swoff(lr + 64, lc) * 2;
    constexpr uint32_t STG = 128 * BK * 2;  // 8KB per stage

    float acc[4][4][4];
#pragma unroll
    for (int i = 0; i < 4; i++)
#pragma unroll
        for (int j = 0; j < 4; j++)
#pragma unroll
            for (int q = 0; q < 4; q++) acc[i][j][q] = 0.f;

    auto load_tile = [&](int kt, int s) {
        const __nv_bfloat16* a = gA + kt * BK;
        const __nv_bfloat16* b = gB + kt * BK;
        uint32_t off = s * STG;
        asm volatile("cp.async.cg.shared.global [%0], [%1], 16;\n" :: "r"(dA0 + off), "l"(a));
        asm volatile("cp.async.cg.shared.global [%0], [%1], 16;\n" :: "r"(dA1 + off), "l"(a + (int64_t)64 * KE));
        asm volatile("cp.async.cg.shared.global [%0], [%1], 16;\n" :: "r"(dB0 + off), "l"(b));
        asm volatile("cp.async.cg.shared.global [%0], [%1], 16;\n" :: "r"(dB1 + off), "l"(b + (int64_t)64 * KE));
        asm volatile("cp.async.commit_group;\n");
    };

    load_tile(0, 0);

    for (int kt = 0; kt < NT; kt++) {
        const int s = kt & 1;
        if (kt + 1 < NT) {
            load_tile(kt + 1, s ^ 1);
            asm volatile("cp.async.wait_group 1;\n" ::: "memory");
        } else {
            asm volatile("cp.async.wait_group 0;\n" ::: "memory");
        }
        __syncthreads();

        const __nv_bfloat16* tA = sA[s];
        const __nv_bfloat16* tB = sB[s];
#pragma unroll
        for (int ks = 0; ks < 2; ks++) {
            const int kb = ks * 16 + 2 * tig;
            uint32_t af[4][4], bf[4][2];
#pragma unroll
            for (int mt = 0; mt < 4; mt++) {
                const int r = wm + mt * 16 + g;
                af[mt][0] = *reinterpret_cast<const uint32_t*>(tA + swoff(r,     kb));
                af[mt][1] = *reinterpret_cast<const uint32_t*>(tA + swoff(r + 8, kb));
                af[mt][2] = *reinterpret_cast<const uint32_t*>(tA + swoff(r,     kb + 8));
                af[mt][3] = *reinterpret_cast<const uint32_t*>(tA + swoff(r + 8, kb + 8));
            }
#pragma unroll
            for (int nt = 0; nt < 4; nt++) {
                const int r = wn + nt * 8 + g;
                bf[nt][0] = *reinterpret_cast<const uint32_t*>(tB + swoff(r, kb));
                bf[nt][1] = *reinterpret_cast<const uint32_t*>(tB + swoff(r, kb + 8));
            }
#pragma unroll
            for (int mt = 0; mt < 4; mt++)
#pragma unroll
                for (int nt = 0; nt < 4; nt++)
                    mma16816(acc[mt][nt], af[mt], bf[nt]);
        }
        __syncthreads();
    }

    // Epilogue
#pragma unroll
    for (int mt = 0; mt < 4; mt++) {
        const int row = m0 + wm + mt * 16 + g;
#pragma unroll
        for (int nt = 0; nt < 4; nt++) {
            const int col = n0 + wn + nt * 8 + 2 * tig;
            const float* c = acc[mt][nt];
            if (EPI == 0) {
                const float b0 = vec[col], b1 = vec[col + 1];
                float* o0 = outF + (int64_t)row * OUT_DIM + col;
                float* o1 = outF + (int64_t)(row + 8) * OUT_DIM + col;
                o0[0] = c[0] + b0;
                o0[1] = c[1] + b1;
                o1[0] = c[2] + b0;
                o1[1] = c[3] + b1;
            } else {
                const float r0 = vec[row], r1 = vec[row + 8];
                __nv_bfloat16* w0 = g_We + (int64_t)row * KE + col;
                __nv_bfloat16* w1 = g_We + (int64_t)(row + 8) * KE + col;
                __nv_bfloat16 h, l;
                float w;
                w = c[0] * r0; split_bf16(w, h, l); w0[0] = h; w0[IN_DIM]     = l; w0[2 * IN_DIM]     = h;
                w = c[1] * r0; split_bf16(w, h, l); w0[1] = h; w0[IN_DIM + 1] = l; w0[2 * IN_DIM + 1] = h;
                w = c[2] * r1; split_bf16(w, h, l); w1[0] = h; w1[IN_DIM]     = l; w1[2 * IN_DIM]     = h;
                w = c[3] * r1; split_bf16(w, h, l); w1[1] = h; w1[IN_DIM + 1] = l; w1[2 * IN_DIM + 1] = h;
            }
        }
    }
}

// ---------------------------------------------------------------------------
// Launch: expand(x, yhat, piT) -> GEMM1 (W = rn * Yhat@Pi, re-split) -> GEMM2
// All launches on the default stream; graph-capturable, allocation-free.
// ---------------------------------------------------------------------------
extern "C" void kernel_launch(void* const* d_in, const int* in_sizes, int n_in,
                              void* d_out, int out_size) {
    const float* x         = (const float*)d_in[0];
    const int*   indices   = (const int*)  d_in[1];
    const float* centroids = (const float*)d_in[2];
    const float* Pi        = (const float*)d_in[3];
    const float* row_norms = (const float*)d_in[4];
    const float* bias      = (const float*)d_in[5];
    float*       out       = (float*)d_out;
    (void)in_sizes; (void)n_in; (void)out_size;

    {
        int64_t tot = (int64_t)MX * IN_DIM / 4;
        expand_x_kernel<<<(unsigned)((tot + 255) / 256), 256>>>(x);
    }
    {
        int64_t tot = (int64_t)OUT_DIM * IN_DIM / 4;
        expand_y_kernel<<<(unsigned)((tot + 255) / 256), 256>>>(indices, centroids);
    }
    {
        dim3 grid(IN_DIM / 32, IN_DIM / 32), blk(32, 8);
        expand_pi_kernel<<<grid, blk>>>(Pi);
    }
    {   // GEMM1: W[o,j], M = OUT_DIM
        dim3 grid(IN_DIM / 128, OUT_DIM / 128);
        gemm_kernel<1><<<grid, 256>>>(row_norms, nullptr);
    }
    {   // GEMM2: out[m,o] = x @ W^T + bias, M = MX
        dim3 grid(OUT_DIM / 128, MX / 128);
        gemm_kernel<0><<<grid, 256>>>(bias, out);
    }
}